// round 11
// baseline (speedup 1.0000x reference)
#include <cuda_runtime.h>
#include <cstdint>

// Problem dims (fixed by reference setup_inputs)
#define TB 4      // batch
#define TT 512    // tokens
#define TD 1024   // d_model
#define TNC 16    // n_concepts
#define TH 256    // init_size
#define NBATCH (TB * TNC)   // 64 batched GEMMs

// ---------------- scratch (__device__ globals; allocation-free rule) ----------------
__device__ float g_wq[(size_t)NBATCH * TT * TH];      // fp32 wq[z][t][h]
__device__ float g_attn_fb[(size_t)NBATCH * TT * TT]; // fp32 attn if d_out has no slot

// ---------------- helpers ----------------
// bf16 hi/lo split of a k-adjacent fp32 pair -> packed bf16x2 regs (lo half = even k)
__device__ __forceinline__ uint2 bf16_pack_split(float f0, float f1) {
    uint32_t h, l;
    asm("cvt.rn.bf16x2.f32 %0, %1, %2;" : "=r"(h) : "f"(f1), "f"(f0));  // hi-half=f1, lo-half=f0
    const float h0 = __uint_as_float(h << 16);
    const float h1 = __uint_as_float(h & 0xFFFF0000u);
    const float l0 = f0 - h0;
    const float l1 = f1 - h1;
    asm("cvt.rn.bf16x2.f32 %0, %1, %2;" : "=r"(l) : "f"(l1), "f"(l0));
    return make_uint2(h, l);   // .x = hi word, .y = lo word
}
__device__ __forceinline__ void mma_bf16(float* d, const uint32_t* a, const uint32_t* b) {
    asm volatile(
        "mma.sync.aligned.m16n8k16.row.col.f32.bf16.bf16.f32 "
        "{%0,%1,%2,%3}, {%4,%5,%6,%7}, {%8,%9}, {%0,%1,%2,%3};"
        : "+f"(d[0]), "+f"(d[1]), "+f"(d[2]), "+f"(d[3])
        : "r"(a[0]), "r"(a[1]), "r"(a[2]), "r"(a[3]), "r"(b[0]), "r"(b[1]));
}

// ---------------- bf16x3 batched GEMM: C tile 128x128 = A[M,K] * B(k,n) ----------------
// SMEM holds PRE-SPLIT interleaved {hi,lo} uint2 per bf16x2 k-pair, k-group-major:
//   pA[stage][kgroup 0..7][row 0..127]  (pad to 132 -> 8B-unit bank = 4*lq+lr, conflict-free)
//   pB[stage][kgroup 0..7][n   0..127]  (same layout; BTR mode fills it via transpose)
// One LDS.64 per fragment register pair (hi+lo together): 24 LDS.64/warp/k16, zero
// split math in the mainloop. Double-buffered, ONE __syncthreads per K-block.
template <int MODE>
__global__ __launch_bounds__(256, 2) void k_gemm_bf16(const float* __restrict__ Ain,
                                                      const float* __restrict__ Bin,
                                                      float* __restrict__ Cout) {
    constexpr int K   = (MODE == 1) ? TD : (MODE == 2) ? TH : TT;
    constexpr int NKB = K / 16;
    constexpr int LDA = K;
    constexpr int LDB = (MODE == 1) ? TH : (MODE == 2) ? TH : TD;
    constexpr int LDC = (MODE == 1) ? TH : (MODE == 2) ? TT : TD;
    constexpr bool BTR = (MODE == 2);          // B stored [n][k] in gmem

    __shared__ uint2 pA[2][8][132];
    __shared__ uint2 pB[2][8][132];

    const int tid = threadIdx.x, wid = tid >> 5, lane = tid & 31;
    const int wm = wid & 1, wn = wid >> 1;     // 2x4 warp grid, warp tile 64x32
    const int lr = lane >> 2, lq = lane & 3;
    const int z = blockIdx.z;
    const int m0 = blockIdx.y * 128;
    const int n0 = blockIdx.x * 128;

    size_t aoff, boff;
    if constexpr (MODE == 1) {
        aoff = (size_t)(z >> 4) * TT * TD;
        boff = (size_t)(z & 15) * TD * TH;
    } else if constexpr (MODE == 2) {
        aoff = (size_t)z * TT * TH;
        boff = aoff;
    } else {
        aoff = (size_t)z * TT * TT;
        boff = (size_t)(z >> 4) * TT * TD;
    }
    const float* pA_ = Ain + aoff + (size_t)m0 * LDA;
    const float* pB_ = BTR ? (Bin + boff + (size_t)n0 * LDB)   // [n][k] row offset
                           : (Bin + boff + n0);                // [k][n] col offset

    float acc[4][4][4];
#pragma unroll
    for (int mi = 0; mi < 4; mi++)
#pragma unroll
        for (int ni = 0; ni < 4; ni++)
#pragma unroll
            for (int e = 0; e < 4; e++) acc[mi][ni][e] = 0.0f;

    // ---- staging: LDG prefetch into regs, then split+STS interleaved {hi,lo} ----
    float4 pfA[2], pfB[2];
    auto prefetch = [&](int kb) {
#pragma unroll
        for (int i = 0; i < 2; i++) {
            const int cid = tid + i * 256;
            const int ar = cid >> 2, ac4 = cid & 3;
            pfA[i] = *reinterpret_cast<const float4*>(pA_ + (size_t)ar * LDA + kb * 16 + ac4 * 4);
        }
        if constexpr (BTR) {
#pragma unroll
            for (int i = 0; i < 2; i++) {
                const int cid = tid + i * 256;
                const int nr = cid >> 2, kc4 = cid & 3;
                pfB[i] = *reinterpret_cast<const float4*>(pB_ + (size_t)nr * LDB + kb * 16 + kc4 * 4);
            }
        } else {
            const int j = tid >> 5, nc = tid & 31;   // k rows 2j,2j+1 ; n-chunk nc
            pfB[0] = *reinterpret_cast<const float4*>(pB_ + (size_t)(kb * 16 + 2 * j) * LDB + nc * 4);
            pfB[1] = *reinterpret_cast<const float4*>(pB_ + (size_t)(kb * 16 + 2 * j + 1) * LDB + nc * 4);
        }
    };
    auto store_stage = [&](int s) {
#pragma unroll
        for (int i = 0; i < 2; i++) {
            const int cid = tid + i * 256;
            const int ar = cid >> 2, ac4 = cid & 3;   // row ar, kgroups 2*ac4, 2*ac4+1
            pA[s][2 * ac4][ar]     = bf16_pack_split(pfA[i].x, pfA[i].y);
            pA[s][2 * ac4 + 1][ar] = bf16_pack_split(pfA[i].z, pfA[i].w);
        }
        if constexpr (BTR) {
#pragma unroll
            for (int i = 0; i < 2; i++) {
                const int cid = tid + i * 256;
                const int nr = cid >> 2, kc4 = cid & 3;
                pB[s][2 * kc4][nr]     = bf16_pack_split(pfB[i].x, pfB[i].y);
                pB[s][2 * kc4 + 1][nr] = bf16_pack_split(pfB[i].z, pfB[i].w);
            }
        } else {
            const int j = tid >> 5, nc = tid & 31;    // kgroup j, n = nc*4..nc*4+3
            pB[s][j][nc * 4 + 0] = bf16_pack_split(pfB[0].x, pfB[1].x);
            pB[s][j][nc * 4 + 1] = bf16_pack_split(pfB[0].y, pfB[1].y);
            pB[s][j][nc * 4 + 2] = bf16_pack_split(pfB[0].z, pfB[1].z);
            pB[s][j][nc * 4 + 3] = bf16_pack_split(pfB[0].w, pfB[1].w);
        }
    };

    prefetch(0);
    store_stage(0);
    __syncthreads();

#pragma unroll 1
    for (int kb = 0; kb < NKB; kb++) {
        const int s = kb & 1;
        if (kb + 1 < NKB) prefetch(kb + 1);   // LDG latency hides under MMAs below

        // ---- fragment loads: one LDS.64 per (hi,lo) register pair, conflict-free ----
        uint2 af[4][4], bf[4][2];
#pragma unroll
        for (int mi = 0; mi < 4; mi++) {
            const int row = wm * 64 + mi * 16 + lr;
            af[mi][0] = pA[s][lq][row];
            af[mi][1] = pA[s][lq][row + 8];
            af[mi][2] = pA[s][lq + 4][row];
            af[mi][3] = pA[s][lq + 4][row + 8];
        }
#pragma unroll
        for (int ni = 0; ni < 4; ni++) {
            const int n = wn * 32 + ni * 8 + lr;
            bf[ni][0] = pB[s][lq][n];
            bf[ni][1] = pB[s][lq + 4][n];
        }

        // pass-major MMA ordering: dependent acc updates are 16 MMAs apart
#pragma unroll
        for (int mi = 0; mi < 4; mi++)
#pragma unroll
            for (int ni = 0; ni < 4; ni++) {
                const uint32_t ah[4] = {af[mi][0].x, af[mi][1].x, af[mi][2].x, af[mi][3].x};
                const uint32_t bh[2] = {bf[ni][0].x, bf[ni][1].x};
                mma_bf16(acc[mi][ni], ah, bh);            // hi*hi
            }
#pragma unroll
        for (int mi = 0; mi < 4; mi++)
#pragma unroll
            for (int ni = 0; ni < 4; ni++) {
                const uint32_t ah[4] = {af[mi][0].x, af[mi][1].x, af[mi][2].x, af[mi][3].x};
                const uint32_t bl[2] = {bf[ni][0].y, bf[ni][1].y};
                mma_bf16(acc[mi][ni], ah, bl);            // hi*lo
            }
#pragma unroll
        for (int mi = 0; mi < 4; mi++)
#pragma unroll
            for (int ni = 0; ni < 4; ni++) {
                const uint32_t al[4] = {af[mi][0].y, af[mi][1].y, af[mi][2].y, af[mi][3].y};
                const uint32_t bh[2] = {bf[ni][0].x, bf[ni][1].x};
                mma_bf16(acc[mi][ni], al, bh);            // lo*hi
            }

        if (kb + 1 < NKB) store_stage(s ^ 1);  // double buffer: writers vs readers disjoint
        __syncthreads();
    }

    // ---- epilogue: fp32 float2 stores (identical to passing R9/R10) ----
    const int rbase = m0 + wm * 64 + lr;
    const int cbase = n0 + wn * 32 + lq * 2;
#pragma unroll
    for (int mi = 0; mi < 4; mi++)
#pragma unroll
        for (int ni = 0; ni < 4; ni++)
#pragma unroll
            for (int h = 0; h < 2; h++) {
                const int row = rbase + mi * 16 + h * 8;
                const int col = cbase + ni * 8;
                float* dst = Cout + (size_t)z * TT * LDC + (size_t)row * LDC + col;
                *reinterpret_cast<float2*>(dst) =
                    make_float2(acc[mi][ni][2 * h], acc[mi][ni][2 * h + 1]);
            }
}

// ---------------- softmax over rows of 512 (unchanged, passing) ----------------
__global__ __launch_bounds__(256) void k_softmax(float* __restrict__ attn) {
    __shared__ float redm[8];
    __shared__ float reds[8];
    float* p = attn + (size_t)blockIdx.x * TT;
    const int tid = threadIdx.x;

    float v0 = p[tid];
    float v1 = p[tid + 256];
    float m = fmaxf(v0, v1);
#pragma unroll
    for (int o = 16; o; o >>= 1) m = fmaxf(m, __shfl_xor_sync(0xffffffffu, m, o));
    if ((tid & 31) == 0) redm[tid >> 5] = m;
    __syncthreads();
    float mAll = redm[0];
#pragma unroll
    for (int w = 1; w < 8; w++) mAll = fmaxf(mAll, redm[w]);

    float e0 = expf(v0 - mAll);
    float e1 = expf(v1 - mAll);
    float s = e0 + e1;
#pragma unroll
    for (int o = 16; o; o >>= 1) s += __shfl_xor_sync(0xffffffffu, s, o);
    if ((tid & 31) == 0) reds[tid >> 5] = s;
    __syncthreads();
    float sAll = 0.0f;
#pragma unroll
    for (int w = 0; w < 8; w++) sAll += reds[w];
    const float inv = 1.0f / sAll;
    p[tid] = e0 * inv;
    p[tid + 256] = e1 * inv;
}

// ---------------- launcher (unchanged, passing) ----------------
extern "C" void kernel_launch(void* const* d_in, const int* in_sizes, int n_in,
                              void* d_out, int out_size) {
    (void)in_sizes; (void)n_in;
    const float* x   = (const float*)d_in[0];
    const float* wqs = (const float*)d_in[1];
    // d_in[2] = w_ks: unused in reference math (faithful to source bug)
    float* out = (float*)d_out;

    const long long EAGG = (long long)NBATCH * TT * TD;  // 33,554,432
    const long long ATTN = (long long)NBATCH * TT * TT;  // 16,777,216

    float* attn;
    if ((long long)out_size >= EAGG + ATTN) {
        attn = out + EAGG;
    } else {
        void* p = nullptr;
        cudaGetSymbolAddress(&p, g_attn_fb);
        attn = (float*)p;
    }
    void* wqp = nullptr;
    cudaGetSymbolAddress(&wqp, g_wq);
    float* wq = (float*)wqp;

    // GEMM1: wq = x @ w_qs
    k_gemm_bf16<1><<<dim3(TH / 128, TT / 128, NBATCH), 256>>>(x, wqs, wq);
    // GEMM2: logits = wq @ wq^T
    k_gemm_bf16<2><<<dim3(TT / 128, TT / 128, NBATCH), 256>>>(wq, wq, attn);
    // softmax in place
    k_softmax<<<NBATCH * TT, 256>>>(attn);
    // GEMM3: e = attn @ x
    k_gemm_bf16<3><<<dim3(TD / 128, TT / 128, NBATCH), 256>>>(attn, x, out);
}

// round 12
// speedup vs baseline: 1.3209x; 1.3209x over previous
#include <cuda_runtime.h>
#include <cstdint>

// Problem dims (fixed by reference setup_inputs)
#define TB 4      // batch
#define TT 512    // tokens
#define TD 1024   // d_model
#define TNC 16    // n_concepts
#define TH 256    // init_size
#define NBATCH (TB * TNC)   // 64 batched GEMMs

// ---------------- scratch (__device__ globals; allocation-free rule) ----------------
__device__ float g_wq[(size_t)NBATCH * TT * TH];      // fp32 wq[z][t][h]
__device__ float g_attn_fb[(size_t)NBATCH * TT * TT]; // fp32 attn if d_out has no slot

// ---------------- helpers ----------------
// bf16 hi/lo split of a k-adjacent fp32 pair -> packed bf16x2 regs (lo half = even k)
__device__ __forceinline__ void bf16_pack_split(float f0, float f1, uint32_t& hi, uint32_t& lo) {
    uint32_t h;
    asm("cvt.rn.bf16x2.f32 %0, %1, %2;" : "=r"(h) : "f"(f1), "f"(f0));  // hi-half=f1, lo-half=f0
    const float h0 = __uint_as_float(h << 16);
    const float h1 = __uint_as_float(h & 0xFFFF0000u);
    const float l0 = f0 - h0;
    const float l1 = f1 - h1;
    asm("cvt.rn.bf16x2.f32 %0, %1, %2;" : "=r"(lo) : "f"(l1), "f"(l0));
    hi = h;
}
__device__ __forceinline__ uint2 bf16_pack_split2(float f0, float f1) {
    uint2 r;
    bf16_pack_split(f0, f1, r.x, r.y);
    return r;
}
__device__ __forceinline__ void mma_bf16(float* d, const uint32_t* a, const uint32_t* b) {
    asm volatile(
        "mma.sync.aligned.m16n8k16.row.col.f32.bf16.bf16.f32 "
        "{%0,%1,%2,%3}, {%4,%5,%6,%7}, {%8,%9}, {%0,%1,%2,%3};"
        : "+f"(d[0]), "+f"(d[1]), "+f"(d[2]), "+f"(d[3])
        : "r"(a[0]), "r"(a[1]), "r"(a[2]), "r"(a[3]), "r"(b[0]), "r"(b[1]));
}

// ---------------- bf16x3 batched GEMM: C tile 128x128 = A[M,K] * B(k,n) ----------------
// A: PRE-SPLIT once per CTA into interleaved {hi,lo} uint2, k-group-major
//    pA[stage][kgroup 0..7][row 0..127] pad 132 -> fragment-load banks 4*lq+lr,
//    conflict-free in both half-warp phases. Unpacked into NAMED ah/al arrays at
//    load time (no call-site temporaries -> no spill, the R11 failure mode).
// B: raw fp32 in SMEM, split at fragment-load time (byte-identical to passing R9;
//    only 2-way redundant, 8 splits/warp/k16).
template <int MODE>
__global__ __launch_bounds__(256, 2) void k_gemm_bf16(const float* __restrict__ Ain,
                                                      const float* __restrict__ Bin,
                                                      float* __restrict__ Cout) {
    constexpr int K   = (MODE == 1) ? TD : (MODE == 2) ? TH : TT;
    constexpr int NKB = K / 16;
    constexpr int LDA = K;
    constexpr int LDB = (MODE == 1) ? TH : (MODE == 2) ? TH : TD;
    constexpr int LDC = (MODE == 1) ? TH : (MODE == 2) ? TT : TD;
    constexpr bool BTR = (MODE == 2);          // B stored [n][k] in gmem
    constexpr int BR = BTR ? 128 : 16;
    constexpr int BC = BTR ? 24  : 132;

    __shared__ uint2 pA[2][8][132];            // 16.9 KB, interleaved {hi,lo}
    __shared__ float sB[2][BR][BC];            // raw fp32 (R9 layout)

    const int tid = threadIdx.x, wid = tid >> 5, lane = tid & 31;
    const int wm = wid & 1, wn = wid >> 1;     // 2x4 warp grid, warp tile 64x32
    const int lr = lane >> 2, lq = lane & 3;
    const int z = blockIdx.z;
    const int m0 = blockIdx.y * 128;
    const int n0 = blockIdx.x * 128;

    size_t aoff, boff;
    if constexpr (MODE == 1) {
        aoff = (size_t)(z >> 4) * TT * TD;
        boff = (size_t)(z & 15) * TD * TH;
    } else if constexpr (MODE == 2) {
        aoff = (size_t)z * TT * TH;
        boff = aoff;
    } else {
        aoff = (size_t)z * TT * TT;
        boff = (size_t)(z >> 4) * TT * TD;
    }
    const float* pA_ = Ain + aoff + (size_t)m0 * LDA;
    const float* pB_ = BTR ? (Bin + boff + (size_t)n0 * LDB)   // [n][k] row offset
                           : (Bin + boff + n0);                // [k][n] col offset

    float acc[4][4][4];
#pragma unroll
    for (int mi = 0; mi < 4; mi++)
#pragma unroll
        for (int ni = 0; ni < 4; ni++)
#pragma unroll
            for (int e = 0; e < 4; e++) acc[mi][ni][e] = 0.0f;

    // ---- staging: LDG prefetch into regs; A splits once here, B stored raw ----
    float4 pfA[2], pfB[2];
    auto prefetch = [&](int kb) {
#pragma unroll
        for (int i = 0; i < 2; i++) {
            const int cid = tid + i * 256;
            const int ar = cid >> 2, ac4 = cid & 3;
            pfA[i] = *reinterpret_cast<const float4*>(pA_ + (size_t)ar * LDA + kb * 16 + ac4 * 4);
        }
        if constexpr (BTR) {
#pragma unroll
            for (int i = 0; i < 2; i++) {
                const int cid = tid + i * 256;
                const int nr = cid >> 2, kc4 = cid & 3;
                pfB[i] = *reinterpret_cast<const float4*>(pB_ + (size_t)nr * LDB + kb * 16 + kc4 * 4);
            }
        } else {
            const int j = tid >> 5, nc = tid & 31;   // k rows 2j,2j+1 ; n-chunk nc
            pfB[0] = *reinterpret_cast<const float4*>(pB_ + (size_t)(kb * 16 + 2 * j) * LDB + nc * 4);
            pfB[1] = *reinterpret_cast<const float4*>(pB_ + (size_t)(kb * 16 + 2 * j + 1) * LDB + nc * 4);
        }
    };
    auto store_stage = [&](int s) {
#pragma unroll
        for (int i = 0; i < 2; i++) {
            const int cid = tid + i * 256;
            const int ar = cid >> 2, ac4 = cid & 3;   // row ar; kgroups 2*ac4, 2*ac4+1
            pA[s][2 * ac4][ar]     = bf16_pack_split2(pfA[i].x, pfA[i].y);
            pA[s][2 * ac4 + 1][ar] = bf16_pack_split2(pfA[i].z, pfA[i].w);
        }
        if constexpr (BTR) {
#pragma unroll
            for (int i = 0; i < 2; i++) {
                const int cid = tid + i * 256;
                const int nr = cid >> 2, kc4 = cid & 3;
                *reinterpret_cast<float4*>(&sB[s][nr][kc4 * 4]) = pfB[i];
            }
        } else {
            const int j = tid >> 5, nc = tid & 31;
            *reinterpret_cast<float4*>(&sB[s][2 * j][nc * 4])     = pfB[0];
            *reinterpret_cast<float4*>(&sB[s][2 * j + 1][nc * 4]) = pfB[1];
        }
    };

    prefetch(0);
    store_stage(0);
    __syncthreads();

#pragma unroll 1
    for (int kb = 0; kb < NKB; kb++) {
        const int s = kb & 1;
        if (kb + 1 < NKB) prefetch(kb + 1);   // LDG latency hides under MMAs below

        // ---- A fragments: LDS.64 from pre-split pA, unpack to NAMED arrays ----
        uint32_t ah[4][4], al[4][4], bh[4][2], bl[4][2];
#pragma unroll
        for (int mi = 0; mi < 4; mi++) {
            const int row = wm * 64 + mi * 16 + lr;
            const uint2 a0 = pA[s][lq][row];
            const uint2 a1 = pA[s][lq][row + 8];
            const uint2 a2 = pA[s][lq + 4][row];
            const uint2 a3 = pA[s][lq + 4][row + 8];
            ah[mi][0] = a0.x; al[mi][0] = a0.y;
            ah[mi][1] = a1.x; al[mi][1] = a1.y;
            ah[mi][2] = a2.x; al[mi][2] = a2.y;
            ah[mi][3] = a3.x; al[mi][3] = a3.y;
        }
        // ---- B fragments: raw fp32 loads + in-register split (R9-identical) ----
#pragma unroll
        for (int ni = 0; ni < 4; ni++) {
            const int n = wn * 32 + ni * 8 + lr;
            float f0, f1, f2, f3;
            if constexpr (BTR) {
                const float2 u0 = *reinterpret_cast<const float2*>(&sB[s][n][2 * lq]);
                const float2 u1 = *reinterpret_cast<const float2*>(&sB[s][n][2 * lq + 8]);
                f0 = u0.x; f1 = u0.y; f2 = u1.x; f3 = u1.y;
            } else {
                f0 = sB[s][2 * lq][n];     f1 = sB[s][2 * lq + 1][n];
                f2 = sB[s][2 * lq + 8][n]; f3 = sB[s][2 * lq + 9][n];
            }
            bf16_pack_split(f0, f1, bh[ni][0], bl[ni][0]);
            bf16_pack_split(f2, f3, bh[ni][1], bl[ni][1]);
        }

        // pass-major MMA ordering (R9-identical; named arrays, static indexing)
#pragma unroll
        for (int mi = 0; mi < 4; mi++)
#pragma unroll
            for (int ni = 0; ni < 4; ni++)
                mma_bf16(acc[mi][ni], ah[mi], bh[ni]);   // hi*hi
#pragma unroll
        for (int mi = 0; mi < 4; mi++)
#pragma unroll
            for (int ni = 0; ni < 4; ni++)
                mma_bf16(acc[mi][ni], ah[mi], bl[ni]);   // hi*lo
#pragma unroll
        for (int mi = 0; mi < 4; mi++)
#pragma unroll
            for (int ni = 0; ni < 4; ni++)
                mma_bf16(acc[mi][ni], al[mi], bh[ni]);   // lo*hi

        if (kb + 1 < NKB) store_stage(s ^ 1);  // double buffer: writers vs readers disjoint
        __syncthreads();
    }

    // ---- epilogue: fp32 float2 stores (identical to passing R9) ----
    const int rbase = m0 + wm * 64 + lr;
    const int cbase = n0 + wn * 32 + lq * 2;
#pragma unroll
    for (int mi = 0; mi < 4; mi++)
#pragma unroll
        for (int ni = 0; ni < 4; ni++)
#pragma unroll
            for (int h = 0; h < 2; h++) {
                const int row = rbase + mi * 16 + h * 8;
                const int col = cbase + ni * 8;
                float* dst = Cout + (size_t)z * TT * LDC + (size_t)row * LDC + col;
                *reinterpret_cast<float2*>(dst) =
                    make_float2(acc[mi][ni][2 * h], acc[mi][ni][2 * h + 1]);
            }
}

// ---------------- softmax over rows of 512 (unchanged, passing) ----------------
__global__ __launch_bounds__(256) void k_softmax(float* __restrict__ attn) {
    __shared__ float redm[8];
    __shared__ float reds[8];
    float* p = attn + (size_t)blockIdx.x * TT;
    const int tid = threadIdx.x;

    float v0 = p[tid];
    float v1 = p[tid + 256];
    float m = fmaxf(v0, v1);
#pragma unroll
    for (int o = 16; o; o >>= 1) m = fmaxf(m, __shfl_xor_sync(0xffffffffu, m, o));
    if ((tid & 31) == 0) redm[tid >> 5] = m;
    __syncthreads();
    float mAll = redm[0];
#pragma unroll
    for (int w = 1; w < 8; w++) mAll = fmaxf(mAll, redm[w]);

    float e0 = expf(v0 - mAll);
    float e1 = expf(v1 - mAll);
    float s = e0 + e1;
#pragma unroll
    for (int o = 16; o; o >>= 1) s += __shfl_xor_sync(0xffffffffu, s, o);
    if ((tid & 31) == 0) reds[tid >> 5] = s;
    __syncthreads();
    float sAll = 0.0f;
#pragma unroll
    for (int w = 0; w < 8; w++) sAll += reds[w];
    const float inv = 1.0f / sAll;
    p[tid] = e0 * inv;
    p[tid + 256] = e1 * inv;
}

// ---------------- launcher (unchanged, passing) ----------------
extern "C" void kernel_launch(void* const* d_in, const int* in_sizes, int n_in,
                              void* d_out, int out_size) {
    (void)in_sizes; (void)n_in;
    const float* x   = (const float*)d_in[0];
    const float* wqs = (const float*)d_in[1];
    // d_in[2] = w_ks: unused in reference math (faithful to source bug)
    float* out = (float*)d_out;

    const long long EAGG = (long long)NBATCH * TT * TD;  // 33,554,432
    const long long ATTN = (long long)NBATCH * TT * TT;  // 16,777,216

    float* attn;
    if ((long long)out_size >= EAGG + ATTN) {
        attn = out + EAGG;
    } else {
        void* p = nullptr;
        cudaGetSymbolAddress(&p, g_attn_fb);
        attn = (float*)p;
    }
    void* wqp = nullptr;
    cudaGetSymbolAddress(&wqp, g_wq);
    float* wq = (float*)wqp;

    // GEMM1: wq = x @ w_qs
    k_gemm_bf16<1><<<dim3(TH / 128, TT / 128, NBATCH), 256>>>(x, wqs, wq);
    // GEMM2: logits = wq @ wq^T
    k_gemm_bf16<2><<<dim3(TT / 128, TT / 128, NBATCH), 256>>>(wq, wq, attn);
    // softmax in place
    k_softmax<<<NBATCH * TT, 256>>>(attn);
    // GEMM3: e = attn @ x
    k_gemm_bf16<3><<<dim3(TD / 128, TT / 128, NBATCH), 256>>>(attn, x, out);
}

// round 14
// speedup vs baseline: 1.6699x; 1.2642x over previous
#include <cuda_runtime.h>
#include <cstdint>

// Problem dims (fixed by reference setup_inputs)
#define TB 4      // batch
#define TT 512    // tokens
#define TD 1024   // d_model
#define TNC 16    // n_concepts
#define TH 256    // init_size
#define NBATCH (TB * TNC)   // 64 batched GEMMs

// ---------------- scratch (__device__ globals; allocation-free rule) ----------------
__device__ float g_wq[(size_t)NBATCH * TT * TH];      // fp32 wq[z][t][h]
__device__ float g_attn_fb[(size_t)NBATCH * TT * TT]; // fp32 attn if d_out has no slot

// ---------------- helpers ----------------
__device__ __forceinline__ uint32_t smem_u32(const void* p) {
    uint32_t a;
    asm("{ .reg .u64 t; cvta.to.shared.u64 t, %1; cvt.u32.u64 %0, t; }" : "=r"(a) : "l"(p));
    return a;
}
__device__ __forceinline__ void cp16(uint32_t dst, const void* src) {
    asm volatile("cp.async.cg.shared.global [%0], [%1], 16;" :: "r"(dst), "l"(src) : "memory");
}
__device__ __forceinline__ void cp_commit() { asm volatile("cp.async.commit_group;" ::: "memory"); }
__device__ __forceinline__ void cp_wait0()  { asm volatile("cp.async.wait_group 0;" ::: "memory"); }

// bf16 hi/lo split of a k-adjacent fp32 pair -> packed bf16x2 regs (lo half = even k)
__device__ __forceinline__ void bf16_pack_split(float f0, float f1, uint32_t& hi, uint32_t& lo) {
    uint32_t h;
    asm("cvt.rn.bf16x2.f32 %0, %1, %2;" : "=r"(h) : "f"(f1), "f"(f0));  // hi-half=f1, lo-half=f0
    const float h0 = __uint_as_float(h << 16);
    const float h1 = __uint_as_float(h & 0xFFFF0000u);
    const float l0 = f0 - h0;
    const float l1 = f1 - h1;
    asm("cvt.rn.bf16x2.f32 %0, %1, %2;" : "=r"(lo) : "f"(l1), "f"(l0));
    hi = h;
}
__device__ __forceinline__ void mma_bf16(float* d, const uint32_t* a, const uint32_t* b) {
    asm volatile(
        "mma.sync.aligned.m16n8k16.row.col.f32.bf16.bf16.f32 "
        "{%0,%1,%2,%3}, {%4,%5,%6,%7}, {%8,%9}, {%0,%1,%2,%3};"
        : "+f"(d[0]), "+f"(d[1]), "+f"(d[2]), "+f"(d[3])
        : "r"(a[0]), "r"(a[1]), "r"(a[2]), "r"(a[3]), "r"(b[0]), "r"(b[1]));
}

// ---------------- bf16x3 batched GEMM: C tile 128x128 = A[M,K] * B(k,n) ----------------
// SMEM holds raw fp32; bf16 hi/lo split happens in registers at fragment-load time
// (the proven-fastest R9 arrangement). Staging uses cp.async double buffering (the
// proven R8 pipeline): no prefetch register residency, no tail STS dependency.
// Layouts: sA[2][128][24] (pad 24 -> conflict-free LDS.64 per half-warp phase);
//          sB direct [2][16][132] / BTR [2][128][24].
template <int MODE>
__global__ __launch_bounds__(256, 2) void k_gemm_bf16(const float* __restrict__ Ain,
                                                      const float* __restrict__ Bin,
                                                      float* __restrict__ Cout) {
    constexpr int K   = (MODE == 1) ? TD : (MODE == 2) ? TH : TT;
    constexpr int NKB = K / 16;
    constexpr int LDA = K;
    constexpr int LDB = (MODE == 1) ? TH : (MODE == 2) ? TH : TD;
    constexpr int LDC = (MODE == 1) ? TH : (MODE == 2) ? TT : TD;
    constexpr bool BTR = (MODE == 2);          // B stored [n][k] in gmem
    constexpr int BR = BTR ? 128 : 16;
    constexpr int BC = BTR ? 24  : 132;

    __shared__ float sA[2][128][24];
    __shared__ float sB[2][BR][BC];

    const int tid = threadIdx.x, wid = tid >> 5, lane = tid & 31;
    const int wm = wid & 1, wn = wid >> 1;     // 2x4 warp grid, warp tile 64x32
    const int lr = lane >> 2, lq = lane & 3;
    const int z = blockIdx.z;
    const int m0 = blockIdx.y * 128;
    const int n0 = blockIdx.x * 128;

    size_t aoff, boff;
    if constexpr (MODE == 1) {
        aoff = (size_t)(z >> 4) * TT * TD;
        boff = (size_t)(z & 15) * TD * TH;
    } else if constexpr (MODE == 2) {
        aoff = (size_t)z * TT * TH;
        boff = aoff;
    } else {
        aoff = (size_t)z * TT * TT;
        boff = (size_t)(z >> 4) * TT * TD;
    }
    const float* pA_ = Ain + aoff + (size_t)m0 * LDA;
    const float* pB_ = BTR ? (Bin + boff + (size_t)n0 * LDB)   // [n][k] row offset
                           : (Bin + boff + n0);                // [k][n] col offset

    float acc[4][4][4];
#pragma unroll
    for (int mi = 0; mi < 4; mi++)
#pragma unroll
        for (int ni = 0; ni < 4; ni++)
#pragma unroll
            for (int e = 0; e < 4; e++) acc[mi][ni][e] = 0.0f;

    // ---- cp.async staging: one 16-wide K block per stage ----
    auto issue_stage = [&](int kb, int s) {
#pragma unroll
        for (int i = 0; i < 2; i++) {
            const int cid = tid + i * 256;
            const int ar = cid >> 2, ac4 = cid & 3;
            cp16(smem_u32(&sA[s][ar][ac4 * 4]),
                 pA_ + (size_t)ar * LDA + kb * 16 + ac4 * 4);
            if constexpr (BTR) {
                const int nr = cid >> 2, kc4 = cid & 3;
                cp16(smem_u32(&sB[s][nr][kc4 * 4]),
                     pB_ + (size_t)nr * LDB + kb * 16 + kc4 * 4);
            } else {
                const int kr = cid >> 5, nc4 = cid & 31;
                cp16(smem_u32(&sB[s][kr][nc4 * 4]),
                     pB_ + (size_t)(kb * 16 + kr) * LDB + nc4 * 4);
            }
        }
        cp_commit();
    };

    issue_stage(0, 0);

#pragma unroll 1
    for (int kb = 0; kb < NKB; kb++) {
        const int s = kb & 1;
        cp_wait0();              // stage s landed (single outstanding group)
        __syncthreads();         // visible to all; prior readers of s^1 done
        if (kb + 1 < NKB) issue_stage(kb + 1, s ^ 1);   // copy overlaps MMAs below

        // ---- fragment load + in-register bf16 hi/lo split (R9-identical) ----
        uint32_t ah[4][4], al[4][4], bh[4][2], bl[4][2];
#pragma unroll
        for (int mi = 0; mi < 4; mi++) {
            const int row = wm * 64 + mi * 16 + lr;
            const float2 v0 = *reinterpret_cast<const float2*>(&sA[s][row][2 * lq]);
            const float2 v1 = *reinterpret_cast<const float2*>(&sA[s][row + 8][2 * lq]);
            const float2 v2 = *reinterpret_cast<const float2*>(&sA[s][row][2 * lq + 8]);
            const float2 v3 = *reinterpret_cast<const float2*>(&sA[s][row + 8][2 * lq + 8]);
            bf16_pack_split(v0.x, v0.y, ah[mi][0], al[mi][0]);
            bf16_pack_split(v1.x, v1.y, ah[mi][1], al[mi][1]);
            bf16_pack_split(v2.x, v2.y, ah[mi][2], al[mi][2]);
            bf16_pack_split(v3.x, v3.y, ah[mi][3], al[mi][3]);
        }
#pragma unroll
        for (int ni = 0; ni < 4; ni++) {
            const int n = wn * 32 + ni * 8 + lr;
            float f0, f1, f2, f3;
            if constexpr (BTR) {
                const float2 u0 = *reinterpret_cast<const float2*>(&sB[s][n][2 * lq]);
                const float2 u1 = *reinterpret_cast<const float2*>(&sB[s][n][2 * lq + 8]);
                f0 = u0.x; f1 = u0.y; f2 = u1.x; f3 = u1.y;
            } else {
                f0 = sB[s][2 * lq][n];     f1 = sB[s][2 * lq + 1][n];
                f2 = sB[s][2 * lq + 8][n]; f3 = sB[s][2 * lq + 9][n];
            }
            bf16_pack_split(f0, f1, bh[ni][0], bl[ni][0]);
            bf16_pack_split(f2, f3, bh[ni][1], bl[ni][1]);
        }

        // pass-major MMA ordering: dependent acc updates are 16 MMAs apart
#pragma unroll
        for (int mi = 0; mi < 4; mi++)
#pragma unroll
            for (int ni = 0; ni < 4; ni++)
                mma_bf16(acc[mi][ni], ah[mi], bh[ni]);   // hi*hi
#pragma unroll
        for (int mi = 0; mi < 4; mi++)
#pragma unroll
            for (int ni = 0; ni < 4; ni++)
                mma_bf16(acc[mi][ni], ah[mi], bl[ni]);   // hi*lo
#pragma unroll
        for (int mi = 0; mi < 4; mi++)
#pragma unroll
            for (int ni = 0; ni < 4; ni++)
                mma_bf16(acc[mi][ni], al[mi], bh[ni]);   // lo*hi
    }

    // ---- epilogue: fp32 float2 stores (identical to passing R9) ----
    const int rbase = m0 + wm * 64 + lr;
    const int cbase = n0 + wn * 32 + lq * 2;
#pragma unroll
    for (int mi = 0; mi < 4; mi++)
#pragma unroll
        for (int ni = 0; ni < 4; ni++)
#pragma unroll
            for (int h = 0; h < 2; h++) {
                const int row = rbase + mi * 16 + h * 8;
                const int col = cbase + ni * 8;
                float* dst = Cout + (size_t)z * TT * LDC + (size_t)row * LDC + col;
                *reinterpret_cast<float2*>(dst) =
                    make_float2(acc[mi][ni][2 * h], acc[mi][ni][2 * h + 1]);
            }
}

// ---------------- softmax over rows of 512 (unchanged, passing) ----------------
__global__ __launch_bounds__(256) void k_softmax(float* __restrict__ attn) {
    __shared__ float redm[8];
    __shared__ float reds[8];
    float* p = attn + (size_t)blockIdx.x * TT;
    const int tid = threadIdx.x;

    float v0 = p[tid];
    float v1 = p[tid + 256];
    float m = fmaxf(v0, v1);
#pragma unroll
    for (int o = 16; o; o >>= 1) m = fmaxf(m, __shfl_xor_sync(0xffffffffu, m, o));
    if ((tid & 31) == 0) redm[tid >> 5] = m;
    __syncthreads();
    float mAll = redm[0];
#pragma unroll
    for (int w = 1; w < 8; w++) mAll = fmaxf(mAll, redm[w]);

    float e0 = expf(v0 - mAll);
    float e1 = expf(v1 - mAll);
    float s = e0 + e1;
#pragma unroll
    for (int o = 16; o; o >>= 1) s += __shfl_xor_sync(0xffffffffu, s, o);
    if ((tid & 31) == 0) reds[tid >> 5] = s;
    __syncthreads();
    float sAll = 0.0f;
#pragma unroll
    for (int w = 0; w < 8; w++) sAll += reds[w];
    const float inv = 1.0f / sAll;
    p[tid] = e0 * inv;
    p[tid + 256] = e1 * inv;
}

// ---------------- launcher (unchanged, passing) ----------------
extern "C" void kernel_launch(void* const* d_in, const int* in_sizes, int n_in,
                              void* d_out, int out_size) {
    (void)in_sizes; (void)n_in;
    const float* x   = (const float*)d_in[0];
    const float* wqs = (const float*)d_in[1];
    // d_in[2] = w_ks: unused in reference math (faithful to source bug)
    float* out = (float*)d_out;

    const long long EAGG = (long long)NBATCH * TT * TD;  // 33,554,432
    const long long ATTN = (long long)NBATCH * TT * TT;  // 16,777,216

    float* attn;
    if ((long long)out_size >= EAGG + ATTN) {
        attn = out + EAGG;
    } else {
        void* p = nullptr;
        cudaGetSymbolAddress(&p, g_attn_fb);
        attn = (float*)p;
    }
    void* wqp = nullptr;
    cudaGetSymbolAddress(&wqp, g_wq);
    float* wq = (float*)wqp;

    // GEMM1: wq = x @ w_qs
    k_gemm_bf16<1><<<dim3(TH / 128, TT / 128, NBATCH), 256>>>(x, wqs, wq);
    // GEMM2: logits = wq @ wq^T
    k_gemm_bf16<2><<<dim3(TT / 128, TT / 128, NBATCH), 256>>>(wq, wq, attn);
    // softmax in place
    k_softmax<<<NBATCH * TT, 256>>>(attn);
    // GEMM3: e = attn @ x
    k_gemm_bf16<3><<<dim3(TD / 128, TT / 128, NBATCH), 256>>>(attn, x, out);
}